// round 3
// baseline (speedup 1.0000x reference)
#include <cuda_runtime.h>
#include <cuda_bf16.h>

// ---------------------------------------------------------------------------
// GridSample 3D, trilinear, zeros padding, align_corners=False
// input  [2, 32, 64, 64, 64] f32
// grid   [2, 96, 96, 96, 3]  f32   (x,y,z) in [-1,1]
// output [2, 32, 96, 96, 96] f32
//
// Strategy:
//   K1: transpose input to channels-last scratch [n][z][y][x][c]
//       -> a spatial voxel's 32 channels are one contiguous 128B line.
//   K2: one warp per output spatial location, lane = channel.
//       8 corner gathers per warp are each a fully-coalesced 128B load.
//       Results staged through a 32x32 shared tile so global writes are
//       coalesced along the Wo dimension per channel.
// ---------------------------------------------------------------------------

#define NB   2
#define C    32
#define D    64
#define HH   64
#define W    64
#define S3   (D * HH * W)      // 262144 spatial voxels per batch
#define DO   96
#define HO   96
#define WO   96

// channels-last scratch: [NB][S3][C] = 16,777,216 floats = 64 MiB
static __device__ float g_scratch[(size_t)NB * S3 * C];

// ---------------------------------------------------------------------------
// K1: [n][c][s] -> [n][s][c] transpose, 32x32 shared tile
// grid: NB * (S3/32) blocks, block (32,8)
// ---------------------------------------------------------------------------
__global__ void transpose_cl_kernel(const float* __restrict__ in) {
    __shared__ float tile[32][33];
    int bid   = blockIdx.x;
    int n     = bid >> 13;               // / (S3/32) = /8192
    int sbase = (bid & 8191) << 5;       // *32
    int tx = threadIdx.x;
    int ty = threadIdx.y;

    const float* inp = in + (size_t)n * C * S3;
#pragma unroll
    for (int i = 0; i < 4; i++) {
        int c = ty + i * 8;
        tile[c][tx] = inp[(size_t)c * S3 + sbase + tx];
    }
    __syncthreads();
    float* dst = g_scratch + (size_t)n * S3 * C;
#pragma unroll
    for (int i = 0; i < 4; i++) {
        int s = ty + i * 8;
        dst[(size_t)(sbase + s) * C + tx] = tile[tx][s];
    }
}

// ---------------------------------------------------------------------------
// K2: sampler. 1024 threads = 32 warps, each warp = one output location,
// lane = channel. grid: NB*DO*HO*(WO/32) = 55296 blocks.
// ---------------------------------------------------------------------------
__global__ __launch_bounds__(1024) void sample_kernel(
    const float* __restrict__ grid, float* __restrict__ out) {
    __shared__ float gsh[96];            // 32 locations * (x,y,z)
    __shared__ float tile[32 * 33];      // [loc][chan], padded

    int bid = blockIdx.x;
    int xg  = bid % 3;  int t = bid / 3;
    int yo  = t % HO;   t /= HO;
    int zo  = t % DO;
    int n   = t / DO;

    int tid = threadIdx.x;

    // cooperative load of the 32 grid coordinate triples
    long gbase = ((((long)n * DO + zo) * HO + yo) * WO + xg * 32) * 3;
    if (tid < 96) gsh[tid] = grid[gbase + tid];
    __syncthreads();

    int w    = tid >> 5;
    int lane = tid & 31;

    float gx = gsh[3 * w + 0];
    float gy = gsh[3 * w + 1];
    float gz = gsh[3 * w + 2];

    // align_corners=False unnormalize: ((g+1)*64 - 1) * 0.5 = (g+1)*32 - 0.5
    float ix = (gx + 1.0f) * 32.0f - 0.5f;
    float iy = (gy + 1.0f) * 32.0f - 0.5f;
    float iz = (gz + 1.0f) * 32.0f - 0.5f;

    float fx = floorf(ix), fy = floorf(iy), fz = floorf(iz);
    float tx = ix - fx, ty = iy - fy, tz = iz - fz;
    int x0 = (int)fx, y0 = (int)fy, z0 = (int)fz;
    int x1 = x0 + 1, y1 = y0 + 1, z1 = z0 + 1;

    // zero-padding: weight = 0 when the corner is out of bounds
    float wx0 = (x0 >= 0 && x0 < W)  ? (1.0f - tx) : 0.0f;
    float wx1 = (x1 >= 0 && x1 < W)  ? tx          : 0.0f;
    float wy0 = (y0 >= 0 && y0 < HH) ? (1.0f - ty) : 0.0f;
    float wy1 = (y1 >= 0 && y1 < HH) ? ty          : 0.0f;
    float wz0 = (z0 >= 0 && z0 < D)  ? (1.0f - tz) : 0.0f;
    float wz1 = (z1 >= 0 && z1 < D)  ? tz          : 0.0f;

    // clamped addresses (loads always in-bounds; weight already zeroed)
    int xc0 = min(max(x0, 0), W - 1),  xc1 = min(max(x1, 0), W - 1);
    int yc0 = min(max(y0, 0), HH - 1), yc1 = min(max(y1, 0), HH - 1);
    int zc0 = min(max(z0, 0), D - 1),  zc1 = min(max(z1, 0), D - 1);

    const float* p = g_scratch +
        ((((size_t)n * D + zc0) * HH + yc0) * W + xc0) * C + lane;
    int ox = (xc1 - xc0) * C;              // 0 or 32
    int oy = (yc1 - yc0) * (W * C);        // 0 or 2048
    int oz = (zc1 - zc0) * (HH * W * C);   // 0 or 131072

    float w00 = wz0 * wy0, w01 = wz0 * wy1;
    float w10 = wz1 * wy0, w11 = wz1 * wy1;

    float acc;
    acc  = (w00 * wx0) * p[0];
    acc += (w00 * wx1) * p[ox];
    acc += (w01 * wx0) * p[oy];
    acc += (w01 * wx1) * p[oy + ox];
    acc += (w10 * wx0) * p[oz];
    acc += (w10 * wx1) * p[oz + ox];
    acc += (w11 * wx0) * p[oz + oy];
    acc += (w11 * wx1) * p[oz + oy + ox];

    tile[w * 33 + lane] = acc;
    __syncthreads();

    // coalesced write: warp index -> channel, lane -> consecutive xo
    int c  = w;
    int xl = lane;
    out[(((size_t)(n * C + c) * DO + zo) * HO + yo) * WO + xg * 32 + xl] =
        tile[xl * 33 + c];
}

extern "C" void kernel_launch(void* const* d_in, const int* in_sizes, int n_in,
                              void* d_out, int out_size) {
    const float* input = (const float*)d_in[0];
    const float* grid  = (const float*)d_in[1];
    float* out = (float*)d_out;

    transpose_cl_kernel<<<NB * (S3 / 32), dim3(32, 8)>>>(input);
    sample_kernel<<<NB * DO * HO * (WO / 32), 1024>>>(grid, out);
}

// round 4
// speedup vs baseline: 2.9146x; 2.9146x over previous
#include <cuda_runtime.h>
#include <cuda_bf16.h>

// ---------------------------------------------------------------------------
// GridSample 3D, trilinear, zeros padding, align_corners=False
// input  [2, 32, 64, 64, 64] f32
// grid   [2, 96, 96, 96, 3]  f32
// output [2, 32, 96, 96, 96] f32
//
// R3: float4-vectorized sampler. Block = 256 threads = 32 locations;
// each location handled by 8 lanes, lane owns 4 channels (LDG.128 per
// corner). 4x fewer load + weight-ALU instructions per output vs R0.
// ---------------------------------------------------------------------------

#define NB   2
#define C    32
#define D    64
#define HH   64
#define W    64
#define S3   (D * HH * W)
#define DO   96
#define HO   96
#define WO   96

// channels-last scratch: [NB][S3][C] = 64 MiB
static __device__ float g_scratch[(size_t)NB * S3 * C];

// ---------------------------------------------------------------------------
// K1: [n][c][s] -> [n][s][c] transpose, 32x32 shared tile
// ---------------------------------------------------------------------------
__global__ void transpose_cl_kernel(const float* __restrict__ in) {
    __shared__ float tile[32][33];
    int bid   = blockIdx.x;
    int n     = bid >> 13;
    int sbase = (bid & 8191) << 5;
    int tx = threadIdx.x;
    int ty = threadIdx.y;

    const float* inp = in + (size_t)n * C * S3;
#pragma unroll
    for (int i = 0; i < 4; i++) {
        int c = ty + i * 8;
        tile[c][tx] = inp[(size_t)c * S3 + sbase + tx];
    }
    __syncthreads();
    float* dst = g_scratch + (size_t)n * S3 * C;
#pragma unroll
    for (int i = 0; i < 4; i++) {
        int s = ty + i * 8;
        dst[(size_t)(sbase + s) * C + tx] = tile[tx][s];
    }
}

// ---------------------------------------------------------------------------
// K2: sampler. 256 threads: loc = tid>>3 (32 locations = one 32-wide
// x-strip), cg = tid&7 (channel group of 4). Corner gathers are LDG.128,
// one 128B transaction per quarter-warp per corner.
// grid: NB*DO*HO*(WO/32) = 55296 blocks.
// ---------------------------------------------------------------------------
__global__ __launch_bounds__(256) void sample_kernel(
    const float* __restrict__ grid, float* __restrict__ out) {
    __shared__ float gsh[96];            // 32 locations * (x,y,z)
    __shared__ float tile[32 * 33];      // [loc][chan], stride 33

    int bid = blockIdx.x;
    int xg  = bid % 3;  int t = bid / 3;
    int yo  = t % HO;   t /= HO;
    int zo  = t % DO;
    int n   = t / DO;

    int tid = threadIdx.x;

    long gbase = ((((long)n * DO + zo) * HO + yo) * WO + xg * 32) * 3;
    if (tid < 96) gsh[tid] = grid[gbase + tid];
    __syncthreads();

    int loc = tid >> 3;      // 0..31 output x within strip
    int cg  = tid & 7;       // channel group (4 channels)

    float gx = gsh[3 * loc + 0];
    float gy = gsh[3 * loc + 1];
    float gz = gsh[3 * loc + 2];

    // align_corners=False: ((g+1)*64 - 1) * 0.5 = (g+1)*32 - 0.5
    float ix = (gx + 1.0f) * 32.0f - 0.5f;
    float iy = (gy + 1.0f) * 32.0f - 0.5f;
    float iz = (gz + 1.0f) * 32.0f - 0.5f;

    float fx = floorf(ix), fy = floorf(iy), fz = floorf(iz);
    float tx = ix - fx, ty = iy - fy, tz = iz - fz;
    int x0 = (int)fx, y0 = (int)fy, z0 = (int)fz;
    int x1 = x0 + 1, y1 = y0 + 1, z1 = z0 + 1;

    float wx0 = (x0 >= 0 && x0 < W)  ? (1.0f - tx) : 0.0f;
    float wx1 = (x1 >= 0 && x1 < W)  ? tx          : 0.0f;
    float wy0 = (y0 >= 0 && y0 < HH) ? (1.0f - ty) : 0.0f;
    float wy1 = (y1 >= 0 && y1 < HH) ? ty          : 0.0f;
    float wz0 = (z0 >= 0 && z0 < D)  ? (1.0f - tz) : 0.0f;
    float wz1 = (z1 >= 0 && z1 < D)  ? tz          : 0.0f;

    int xc0 = min(max(x0, 0), W - 1),  xc1 = min(max(x1, 0), W - 1);
    int yc0 = min(max(y0, 0), HH - 1), yc1 = min(max(y1, 0), HH - 1);
    int zc0 = min(max(z0, 0), D - 1),  zc1 = min(max(z1, 0), D - 1);

    const float4* p = (const float4*)(g_scratch +
        ((((size_t)n * D + zc0) * HH + yc0) * W + xc0) * C) + cg;
    int ox = (xc1 - xc0) * (C / 4);            // 0 or 8   (float4 units)
    int oy = (yc1 - yc0) * (W * C / 4);        // 0 or 512
    int oz = (zc1 - zc0) * (HH * W * C / 4);   // 0 or 32768

    float w00 = wz0 * wy0, w01 = wz0 * wy1;
    float w10 = wz1 * wy0, w11 = wz1 * wy1;

    float w000 = w00 * wx0, w001 = w00 * wx1;
    float w010 = w01 * wx0, w011 = w01 * wx1;
    float w100 = w10 * wx0, w101 = w10 * wx1;
    float w110 = w11 * wx0, w111 = w11 * wx1;

    float4 v;
    float4 a = make_float4(0.f, 0.f, 0.f, 0.f);
#define ACC(PTR, WW) \
    v = (PTR); \
    a.x += (WW) * v.x; a.y += (WW) * v.y; a.z += (WW) * v.z; a.w += (WW) * v.w;

    ACC(p[0],            w000)
    ACC(p[ox],           w001)
    ACC(p[oy],           w010)
    ACC(p[oy + ox],      w011)
    ACC(p[oz],           w100)
    ACC(p[oz + ox],      w101)
    ACC(p[oz + oy],      w110)
    ACC(p[oz + oy + ox], w111)
#undef ACC

    // stage: tile[loc][cg*4 + j]; banks (loc + 4*cg + j) distinct per warp
    int row = loc * 33 + cg * 4;
    tile[row + 0] = a.x;
    tile[row + 1] = a.y;
    tile[row + 2] = a.z;
    tile[row + 3] = a.w;
    __syncthreads();

    // coalesced writes: warp w covers channels 4w..4w+3, lane = xo
    int w    = tid >> 5;
    int lane = tid & 31;
    size_t obase = (((size_t)(n * C) * DO + zo) * HO + yo) * WO + xg * 32 + lane;
#pragma unroll
    for (int i = 0; i < 4; i++) {
        int c = w * 4 + i;
        out[obase + (size_t)c * (DO * HO * WO)] = tile[lane * 33 + c];
    }
}

extern "C" void kernel_launch(void* const* d_in, const int* in_sizes, int n_in,
                              void* d_out, int out_size) {
    const float* input = (const float*)d_in[0];
    const float* grid  = (const float*)d_in[1];
    float* out = (float*)d_out;

    transpose_cl_kernel<<<NB * (S3 / 32), dim3(32, 8)>>>(input);
    sample_kernel<<<NB * DO * HO * (WO / 32), 256>>>(grid, out);
}